// round 4
// baseline (speedup 1.0000x reference)
#include <cuda_runtime.h>

// SpikingLayer: input (B*T, 32*32*32) f32, B=16, T=128.
// Per (b, feat): state = max(syn_t + state - act, -1); act = floor(max(state, 0)).
//   (act identity: s>0 ? floor(s) : 0  ==  floor(max(s,0)) — saves FSETP+SEL.)
//
// Pure HBM stream: 268MB in + 268MB out = 537MB through LTS. R1 measured
// 6.84 TB/s = at the B300 LTS chip cap (~6300 B/cyc, path-independent), so
// this kernel is at roofline. R3 = R1's best shape (4-step software pipeline,
// 8 LDG.128 in flight per thread) + shorter state dependency chain.

#define T_STEPS 128
#define FEAT    32768            // 32*32*32
#define F4      (FEAT / 4)       // 8192 float4 per time step
#define BATCH   16

__global__ __launch_bounds__(256, 4)
void spiking_layer_kernel(const float4* __restrict__ x, float4* __restrict__ out) {
    const unsigned tid = blockIdx.x * blockDim.x + threadIdx.x;  // 0 .. 131071
    const unsigned b = tid >> 13;        // / 8192
    const unsigned f = tid & (F4 - 1);   // % 8192

    const size_t base = (size_t)b * T_STEPS * F4 + f;
    const float4* __restrict__ in = x + base;
    float4* __restrict__ o = out + base;

    float sx = 0.f, sy = 0.f, sz = 0.f, sw = 0.f;   // membrane state
    float ax = 0.f, ay = 0.f, az = 0.f, aw = 0.f;   // last activation

    #define STEP_STORE(v, t_idx)                                          \
        sx = fmaxf(v.x + sx - ax, -1.0f);                                 \
        sy = fmaxf(v.y + sy - ay, -1.0f);                                 \
        sz = fmaxf(v.z + sz - az, -1.0f);                                 \
        sw = fmaxf(v.w + sw - aw, -1.0f);                                 \
        ax = floorf(fmaxf(sx, 0.f));                                      \
        ay = floorf(fmaxf(sy, 0.f));                                      \
        az = floorf(fmaxf(sz, 0.f));                                      \
        aw = floorf(fmaxf(sw, 0.f));                                      \
        __stcs(o + (size_t)(t_idx) * F4, make_float4(ax, ay, az, aw));

    // Prologue: chunk 0 (4 steps)
    float4 c0 = __ldcs(in + 0 * (size_t)F4);
    float4 c1 = __ldcs(in + 1 * (size_t)F4);
    float4 c2 = __ldcs(in + 2 * (size_t)F4);
    float4 c3 = __ldcs(in + 3 * (size_t)F4);

    #pragma unroll 1
    for (int t = 0; t < T_STEPS - 4; t += 4) {
        // Prefetch next chunk first: keeps up to 8 LDG.128 in flight per thread
        float4 n0 = __ldcs(in + (size_t)(t + 4) * F4);
        float4 n1 = __ldcs(in + (size_t)(t + 5) * F4);
        float4 n2 = __ldcs(in + (size_t)(t + 6) * F4);
        float4 n3 = __ldcs(in + (size_t)(t + 7) * F4);

        STEP_STORE(c0, t + 0);
        STEP_STORE(c1, t + 1);
        STEP_STORE(c2, t + 2);
        STEP_STORE(c3, t + 3);

        c0 = n0; c1 = n1; c2 = n2; c3 = n3;
    }

    // Epilogue: t = 124..127
    STEP_STORE(c0, T_STEPS - 4);
    STEP_STORE(c1, T_STEPS - 3);
    STEP_STORE(c2, T_STEPS - 2);
    STEP_STORE(c3, T_STEPS - 1);

    #undef STEP_STORE
}

extern "C" void kernel_launch(void* const* d_in, const int* in_sizes, int n_in,
                              void* d_out, int out_size) {
    const float4* x = (const float4*)d_in[0];
    float4* o = (float4*)d_out;
    const int total_threads = BATCH * F4;          // 131072
    spiking_layer_kernel<<<total_threads / 256, 256>>>(x, o);
}

// round 5
// speedup vs baseline: 1.0090x; 1.0090x over previous
#include <cuda_runtime.h>

// SpikingLayer: input (B*T, 32*32*32) f32, B=16, T=128.
// Per (b, feat): state = max(syn_t + state - act, -1); act = floor(max(state, 0)).
//
// Pure HBM stream: 268MB in + 268MB out. DRAM-bound at ~76-78% of 8TB/s;
// 50/50 R/W turnaround bounds practical peak ~80-85%. R4 = best-measured
// launch shape (1024 CTAs x 128 thr, R1) + shortened recurrence chain (R3)
// + 6-deep prefetch pipeline (12 LDG.128 in flight per thread).

#define T_STEPS 128
#define FEAT    32768            // 32*32*32
#define F4      (FEAT / 4)       // 8192 float4 per time step
#define BATCH   16
#define DEPTH   6                // pipeline chunk: 6 time steps (128 = 4 + 6*20 + 4... no:
                                 // 128 % 6 != 0 -> handle with 4+6k? use epilogue loop)

__global__ __launch_bounds__(128, 8)
void spiking_layer_kernel(const float4* __restrict__ x, float4* __restrict__ out) {
    const unsigned tid = blockIdx.x * blockDim.x + threadIdx.x;  // 0 .. 131071
    const unsigned b = tid >> 13;        // / 8192
    const unsigned f = tid & (F4 - 1);   // % 8192

    const size_t base = (size_t)b * T_STEPS * F4 + f;
    const float4* __restrict__ in = x + base;
    float4* __restrict__ o = out + base;

    float sx = 0.f, sy = 0.f, sz = 0.f, sw = 0.f;   // membrane state
    float ax = 0.f, ay = 0.f, az = 0.f, aw = 0.f;   // last activation

    #define STEP_STORE(v, t_idx)                                          \
        sx = fmaxf(v.x + sx - ax, -1.0f);                                 \
        sy = fmaxf(v.y + sy - ay, -1.0f);                                 \
        sz = fmaxf(v.z + sz - az, -1.0f);                                 \
        sw = fmaxf(v.w + sw - aw, -1.0f);                                 \
        ax = floorf(fmaxf(sx, 0.f));                                      \
        ay = floorf(fmaxf(sy, 0.f));                                      \
        az = floorf(fmaxf(sz, 0.f));                                      \
        aw = floorf(fmaxf(sw, 0.f));                                      \
        __stcs(o + (size_t)(t_idx) * F4, make_float4(ax, ay, az, aw));

    // Prologue: load chunk for t = 0..5  (128 = 6*21 + 2; main loop covers
    // t=0..119 in 20 iterations, epilogue handles t=120..127 with 8 steps:
    // simpler: 128 = 8 + 6*20 -> prologue chunk of 8? Keep it regular:
    // use DEPTH=6 chunks for t in [0,120), then a 8-step tail prefetched inside.)

    float4 c0 = __ldcs(in + 0 * (size_t)F4);
    float4 c1 = __ldcs(in + 1 * (size_t)F4);
    float4 c2 = __ldcs(in + 2 * (size_t)F4);
    float4 c3 = __ldcs(in + 3 * (size_t)F4);
    float4 c4 = __ldcs(in + 4 * (size_t)F4);
    float4 c5 = __ldcs(in + 5 * (size_t)F4);

    // Main: 20 iterations cover t = 0..113 computed, prefetching t+6..t+11.
    // After loop, c* holds t = 114..119; tail loads t = 120..127 (8 steps).
    #pragma unroll 1
    for (int t = 0; t < T_STEPS - 14; t += DEPTH) {
        float4 n0 = __ldcs(in + (size_t)(t + 6)  * F4);
        float4 n1 = __ldcs(in + (size_t)(t + 7)  * F4);
        float4 n2 = __ldcs(in + (size_t)(t + 8)  * F4);
        float4 n3 = __ldcs(in + (size_t)(t + 9)  * F4);
        float4 n4 = __ldcs(in + (size_t)(t + 10) * F4);
        float4 n5 = __ldcs(in + (size_t)(t + 11) * F4);

        STEP_STORE(c0, t + 0);
        STEP_STORE(c1, t + 1);
        STEP_STORE(c2, t + 2);
        STEP_STORE(c3, t + 3);
        STEP_STORE(c4, t + 4);
        STEP_STORE(c5, t + 5);

        c0 = n0; c1 = n1; c2 = n2; c3 = n3; c4 = n4; c5 = n5;
    }

    // Tail: c* = t 114..119; prefetch t 120..127, then finish.
    {
        const int t = T_STEPS - 14;  // 114
        float4 n0 = __ldcs(in + (size_t)(t + 6)  * F4);
        float4 n1 = __ldcs(in + (size_t)(t + 7)  * F4);
        float4 n2 = __ldcs(in + (size_t)(t + 8)  * F4);
        float4 n3 = __ldcs(in + (size_t)(t + 9)  * F4);
        float4 n4 = __ldcs(in + (size_t)(t + 10) * F4);
        float4 n5 = __ldcs(in + (size_t)(t + 11) * F4);
        float4 n6 = __ldcs(in + (size_t)(t + 12) * F4);
        float4 n7 = __ldcs(in + (size_t)(t + 13) * F4);

        STEP_STORE(c0, t + 0);
        STEP_STORE(c1, t + 1);
        STEP_STORE(c2, t + 2);
        STEP_STORE(c3, t + 3);
        STEP_STORE(c4, t + 4);
        STEP_STORE(c5, t + 5);

        STEP_STORE(n0, t + 6);
        STEP_STORE(n1, t + 7);
        STEP_STORE(n2, t + 8);
        STEP_STORE(n3, t + 9);
        STEP_STORE(n4, t + 10);
        STEP_STORE(n5, t + 11);
        STEP_STORE(n6, t + 12);
        STEP_STORE(n7, t + 13);
    }

    #undef STEP_STORE
}

extern "C" void kernel_launch(void* const* d_in, const int* in_sizes, int n_in,
                              void* d_out, int out_size) {
    const float4* x = (const float4*)d_in[0];
    float4* o = (float4*)d_out;
    const int total_threads = BATCH * F4;          // 131072
    spiking_layer_kernel<<<total_threads / 128, 128>>>(x, o);
}

// round 6
// speedup vs baseline: 1.0284x; 1.0193x over previous
#include <cuda_runtime.h>

// SpikingLayer: input (B*T, 32*32*32) f32, B=16, T=128.
// Per (b, feat): state = max(syn_t + state - act, -1); act = s>0 ? floor(s) : 0.
//
// Pure HBM stream: 268MB in + 268MB out; DRAM-bound (~6.2 TB/s mixed R/W).
// Measured optimum across R0-R4: 1024 CTAs x 128 threads, 4-deep prefetch
// pipeline (8 LDG.128 in flight/thread). R5 adds store batching: all 4
// recurrence steps of a chunk complete before the 4 STG.128 issue as a burst,
// separating the warp's load and store phases for the memory controller.

#define T_STEPS 128
#define FEAT    32768            // 32*32*32
#define F4      (FEAT / 4)       // 8192 float4 per time step
#define BATCH   16

__global__ __launch_bounds__(128)
void spiking_layer_kernel(const float4* __restrict__ x, float4* __restrict__ out) {
    const unsigned tid = blockIdx.x * blockDim.x + threadIdx.x;  // 0 .. 131071
    const unsigned b = tid >> 13;        // / 8192
    const unsigned f = tid & (F4 - 1);   // % 8192

    const size_t base = (size_t)b * T_STEPS * F4 + f;
    const float4* __restrict__ in = x + base;
    float4* __restrict__ o = out + base;

    float sx = 0.f, sy = 0.f, sz = 0.f, sw = 0.f;   // membrane state
    float ax = 0.f, ay = 0.f, az = 0.f, aw = 0.f;   // last activation

    // One recurrence step: consume input v, produce act into r (float4).
    #define STEP(v, r)                                                    \
        sx = fmaxf(v.x + sx - ax, -1.0f);                                 \
        sy = fmaxf(v.y + sy - ay, -1.0f);                                 \
        sz = fmaxf(v.z + sz - az, -1.0f);                                 \
        sw = fmaxf(v.w + sw - aw, -1.0f);                                 \
        ax = (sx > 0.f) ? floorf(sx) : 0.f;                               \
        ay = (sy > 0.f) ? floorf(sy) : 0.f;                               \
        az = (sz > 0.f) ? floorf(sz) : 0.f;                               \
        aw = (sw > 0.f) ? floorf(sw) : 0.f;                               \
        r = make_float4(ax, ay, az, aw);

    // Prologue: chunk 0 (4 steps)
    float4 c0 = __ldcs(in + 0 * (size_t)F4);
    float4 c1 = __ldcs(in + 1 * (size_t)F4);
    float4 c2 = __ldcs(in + 2 * (size_t)F4);
    float4 c3 = __ldcs(in + 3 * (size_t)F4);

    #pragma unroll 1
    for (int t = 0; t < T_STEPS - 4; t += 4) {
        // Load burst: prefetch next chunk (up to 8 LDG.128 in flight)
        float4 n0 = __ldcs(in + (size_t)(t + 4) * F4);
        float4 n1 = __ldcs(in + (size_t)(t + 5) * F4);
        float4 n2 = __ldcs(in + (size_t)(t + 6) * F4);
        float4 n3 = __ldcs(in + (size_t)(t + 7) * F4);

        // Compute phase: 4 serial recurrence steps, results buffered
        float4 r0, r1, r2, r3;
        STEP(c0, r0);
        STEP(c1, r1);
        STEP(c2, r2);
        STEP(c3, r3);

        // Store burst
        __stcs(o + (size_t)(t + 0) * F4, r0);
        __stcs(o + (size_t)(t + 1) * F4, r1);
        __stcs(o + (size_t)(t + 2) * F4, r2);
        __stcs(o + (size_t)(t + 3) * F4, r3);

        c0 = n0; c1 = n1; c2 = n2; c3 = n3;
    }

    // Epilogue: t = 124..127
    {
        const int t = T_STEPS - 4;
        float4 r0, r1, r2, r3;
        STEP(c0, r0);
        STEP(c1, r1);
        STEP(c2, r2);
        STEP(c3, r3);
        __stcs(o + (size_t)(t + 0) * F4, r0);
        __stcs(o + (size_t)(t + 1) * F4, r1);
        __stcs(o + (size_t)(t + 2) * F4, r2);
        __stcs(o + (size_t)(t + 3) * F4, r3);
    }

    #undef STEP
}

extern "C" void kernel_launch(void* const* d_in, const int* in_sizes, int n_in,
                              void* d_out, int out_size) {
    const float4* x = (const float4*)d_in[0];
    float4* o = (float4*)d_out;
    const int total_threads = BATCH * F4;          // 131072
    spiking_layer_kernel<<<total_threads / 128, 128>>>(x, o);
}

// round 8
// speedup vs baseline: 1.0350x; 1.0064x over previous
#include <cuda_runtime.h>

// SpikingLayer: input (B*T, 32*32*32) f32, B=16, T=128.
// Per (b, feat): state = max(syn_t + state - act, -1); act = s>0 ? floor(s) : 0.
//
// Pure HBM stream: 268MB in + 268MB out. Measured plateau across 6 variants:
// ~6.0-6.2 TB/s = the B300 full-chip LTS throughput cap (~6300 B/cyc,
// path-independent per B300_MICROARCH.md - TMA staging cannot beat it).
// Both streams are compulsory (nonlinear recurrence, f32 output). This is
// the empirically-best configuration (R1): 1024 CTAs x 128 threads, 4-deep
// software-pipelined prefetch (8 LDG.128 in flight per thread), streaming
// cache hints both directions.

#define T_STEPS 128
#define FEAT    32768            // 32*32*32
#define F4      (FEAT / 4)       // 8192 float4 per time step
#define BATCH   16

__global__ __launch_bounds__(128, 8)
void spiking_layer_kernel(const float4* __restrict__ x, float4* __restrict__ out) {
    const unsigned tid = blockIdx.x * blockDim.x + threadIdx.x;  // 0 .. 131071
    const unsigned b = tid >> 13;        // / 8192
    const unsigned f = tid & (F4 - 1);   // % 8192

    const size_t base = (size_t)b * T_STEPS * F4 + f;
    const float4* __restrict__ in = x + base;
    float4* __restrict__ o = out + base;

    float sx = 0.f, sy = 0.f, sz = 0.f, sw = 0.f;   // membrane state
    float ax = 0.f, ay = 0.f, az = 0.f, aw = 0.f;   // last activation

    #define STEP_STORE(v, t_idx)                                          \
        sx = fmaxf(v.x + sx - ax, -1.0f);                                 \
        sy = fmaxf(v.y + sy - ay, -1.0f);                                 \
        sz = fmaxf(v.z + sz - az, -1.0f);                                 \
        sw = fmaxf(v.w + sw - aw, -1.0f);                                 \
        ax = (sx > 0.f) ? floorf(sx) : 0.f;                               \
        ay = (sy > 0.f) ? floorf(sy) : 0.f;                               \
        az = (sz > 0.f) ? floorf(sz) : 0.f;                               \
        aw = (sw > 0.f) ? floorf(sw) : 0.f;                               \
        __stcs(o + (size_t)(t_idx) * F4, make_float4(ax, ay, az, aw));

    // Prologue: load chunk 0
    float4 c0 = __ldcs(in + 0 * (size_t)F4);
    float4 c1 = __ldcs(in + 1 * (size_t)F4);
    float4 c2 = __ldcs(in + 2 * (size_t)F4);
    float4 c3 = __ldcs(in + 3 * (size_t)F4);

    #pragma unroll 1
    for (int t = 0; t < T_STEPS - 4; t += 4) {
        // Prefetch next chunk before touching current one (keeps 8 loads in flight)
        float4 n0 = __ldcs(in + (size_t)(t + 4) * F4);
        float4 n1 = __ldcs(in + (size_t)(t + 5) * F4);
        float4 n2 = __ldcs(in + (size_t)(t + 6) * F4);
        float4 n3 = __ldcs(in + (size_t)(t + 7) * F4);

        STEP_STORE(c0, t + 0);
        STEP_STORE(c1, t + 1);
        STEP_STORE(c2, t + 2);
        STEP_STORE(c3, t + 3);

        c0 = n0; c1 = n1; c2 = n2; c3 = n3;
    }

    // Epilogue: last chunk (t = 124..127)
    STEP_STORE(c0, T_STEPS - 4);
    STEP_STORE(c1, T_STEPS - 3);
    STEP_STORE(c2, T_STEPS - 2);
    STEP_STORE(c3, T_STEPS - 1);

    #undef STEP_STORE
}

extern "C" void kernel_launch(void* const* d_in, const int* in_sizes, int n_in,
                              void* d_out, int out_size) {
    const float4* x = (const float4*)d_in[0];
    float4* o = (float4*)d_out;
    const int total_threads = BATCH * F4;          // 131072
    spiking_layer_kernel<<<total_threads / 128, 128>>>(x, o);
}